// round 7
// baseline (speedup 1.0000x reference)
#include <cuda_runtime.h>
#include <cstdint>
#include <cstddef>

// ---------------- problem constants ----------------
#define BATCH   16384
#define SEQ     15
#define DIM     512
#define UNITS   32
#define NQK     64

// ---------------- fused kernel tiling ----------------
#define NB        2                    // batches per CTA
#define ROWS      30                   // NB*SEQ
#define ROWS_PAD  32
#define THREADS   256
#define GRID      (BATCH / NB)         // 8192
#define KCHUNK    32
#define NCHUNKS   (DIM / KCHUNK)       // 16
#define NSTAGE    3

#define XS_ST     516                  // x tile row stride (floats), 16B aligned
#define WS_ST     68                   // W chunk row stride
#define QK_ST     68
#define EAT_ST    16

#define XS_FLOATS (ROWS_PAD * XS_ST)          // 16512
#define WS_FLOATS (KCHUNK * WS_ST)            // 2176
#define QK_FLOATS (ROWS_PAD * QK_ST)          // 2176 (rows 30,31 unused)
#define EAT_FLOATS (NB * SEQ * EAT_ST)        // 480

#define XS_OFF   0
#define WS_OFF   (XS_OFF + XS_FLOATS)                    // 16512
#define QK_OFF   (WS_OFF + NSTAGE * WS_FLOATS)           // 23040
#define EAT_OFF  (QK_OFF + QK_FLOATS)                    // 25216
#define WA_OFF   (EAT_OFF + EAT_FLOATS)                  // 25696
#define SMEM_FLOATS (WA_OFF + UNITS)                     // 25728
#define SMEM_BYTES  (SMEM_FLOATS * 4)                    // 102912 -> 2 CTAs/SM

// ---------------- helpers ----------------
__device__ __forceinline__ void cp16(void* dst, const void* src) {
    uint32_t d = (uint32_t)__cvta_generic_to_shared(dst);
    asm volatile("cp.async.cg.shared.global [%0], [%1], 16;" :: "r"(d), "l"(src));
}
#define CP_COMMIT() asm volatile("cp.async.commit_group;")
#define CP_WAIT1()  asm volatile("cp.async.wait_group 1;")
#define CP_WAIT0()  asm volatile("cp.async.wait_group 0;")

__device__ __forceinline__ void mma_tf32(float* c,
                                         uint32_t a0, uint32_t a1, uint32_t a2, uint32_t a3,
                                         uint32_t b0, uint32_t b1) {
    asm volatile(
        "mma.sync.aligned.m16n8k8.row.col.f32.tf32.tf32.f32 "
        "{%0,%1,%2,%3}, {%4,%5,%6,%7}, {%8,%9}, {%0,%1,%2,%3};"
        : "+f"(c[0]), "+f"(c[1]), "+f"(c[2]), "+f"(c[3])
        : "r"(a0), "r"(a1), "r"(a2), "r"(a3), "r"(b0), "r"(b1));
}

__device__ __forceinline__ float rcp_fast(float v) {
    float r;
    asm("rcp.approx.f32 %0, %1;" : "=f"(r) : "f"(v));
    return r;
}

// ================= fused kernel =================
__global__ __launch_bounds__(THREADS, 2)
void sda_fused2_kernel(const float* __restrict__ x,
                       const float* __restrict__ Wt,
                       const float* __restrict__ Wx,
                       const float* __restrict__ bh,
                       const float* __restrict__ Wa,
                       const float* __restrict__ ba,
                       float* __restrict__ out)
{
    extern __shared__ float sm[];
    float* xs  = sm + XS_OFF;
    float* qs  = sm + QK_OFF;
    float* eat = sm + EAT_OFF;
    float* was = sm + WA_OFF;

    const int tid  = threadIdx.x;
    const int lane = tid & 31;
    const int w    = tid >> 5;          // 0..7
    const long long rowbase = (long long)blockIdx.x * ROWS;

    // ---- stage W chunk [KCHUNK k][64 n] into ring buffer ----
    auto issueW = [&](int stage, int kc) {
        float* ws = sm + WS_OFF + stage * WS_FLOATS;
        #pragma unroll
        for (int r = 0; r < 2; r++) {
            int e  = tid + THREADS * r;   // 0..511
            int k  = e >> 4;              // 0..31
            int n4 = e & 15;              // 0..15
            const float* src = (n4 < 8)
                ? Wt + (size_t)(kc + k) * UNITS + n4 * 4
                : Wx + (size_t)(kc + k) * UNITS + (n4 - 8) * 4;
            cp16(ws + k * WS_ST + n4 * 4, src);
        }
    };

    // ---- prologue: x tile (30 rows, resident) + W chunks 0,1 ----
    #pragma unroll
    for (int r = 0; r < 15; r++) {
        int s   = tid + THREADS * r;      // 0..3839
        int row = s >> 7;                 // 0..29
        int c4  = s & 127;                // 0..127
        cp16(xs + row * XS_ST + c4 * 4,
             x + (rowbase + row) * DIM + c4 * 4);
    }
    // zero pad rows 30,31 (read by mma A-fragments, results discarded)
    {
        int s = tid;                      // 258 float4 slots over 2 rows
        if (s < 2 * (XS_ST / 4)) {
            int row = 30 + s / (XS_ST / 4);
            int c4  = s % (XS_ST / 4);
            *(float4*)(xs + row * XS_ST + c4 * 4) = make_float4(0.f, 0.f, 0.f, 0.f);
        }
    }
    if (tid < UNITS) was[tid] = Wa[tid];
    const float bav = __ldg(ba);

    issueW(0, 0);
    CP_COMMIT();                          // group: x + W0
    issueW(1, KCHUNK);
    CP_COMMIT();                          // group: W1

    // ---- phase 1: qk = x @ [Wt|Wx] + bh ----
    // warp w: m-tile mt=w&1 (rows mt*16..+15), n-slice ns=w>>2? -> ns = w>>1
    const int mt = w & 1;
    const int ns = w >> 1;                // 0..3 -> cols ns*16 .. ns*16+15
    const int g  = lane >> 2;
    const int tg = lane & 3;

    float acc[2][4];
    #pragma unroll
    for (int n = 0; n < 2; n++)
        #pragma unroll
        for (int q = 0; q < 4; q++) acc[n][q] = 0.f;

    int stage = 0;
    for (int c = 0; c < NCHUNKS; c++) {
        if (c == NCHUNKS - 1) { CP_WAIT0(); } else { CP_WAIT1(); }
        __syncthreads();   // chunk c (and x on c==0) visible; readers of reissue buf done

        if (c + 2 < NCHUNKS) {
            int nsg = stage + 2; if (nsg >= NSTAGE) nsg -= NSTAGE;
            issueW(nsg, (c + 2) * KCHUNK);
            CP_COMMIT();
        }

        float* ws = sm + WS_OFF + stage * WS_FLOATS;
        const int kc = c * KCHUNK;

        #pragma unroll
        for (int k8 = 0; k8 < 4; k8++) {
            const int kb = k8 * 8;
            const float* ar = xs + (mt * 16 + g) * XS_ST + kc + kb + tg;
            uint32_t a0 = __float_as_uint(ar[0]);
            uint32_t a1 = __float_as_uint(ar[8 * XS_ST]);
            uint32_t a2 = __float_as_uint(ar[4]);
            uint32_t a3 = __float_as_uint(ar[8 * XS_ST + 4]);
            const float* br = ws + (kb + tg) * WS_ST + ns * 16 + g;
            #pragma unroll
            for (int nt = 0; nt < 2; nt++) {
                mma_tf32(acc[nt], a0, a1, a2, a3,
                         __float_as_uint(br[nt * 8]),
                         __float_as_uint(br[4 * WS_ST + nt * 8]));
            }
        }
        if (++stage >= NSTAGE) stage -= NSTAGE;
    }

    // epilogue: qk -> smem (+bh on cols < 32), skip pad rows
    {
        const int r0 = mt * 16 + g;
        const int r1 = r0 + 8;
        #pragma unroll
        for (int nt = 0; nt < 2; nt++) {
            int cc = ns * 16 + nt * 8 + tg * 2;
            float b0 = (cc     < UNITS) ? __ldg(bh + cc)     : 0.f;
            float b1 = (cc + 1 < UNITS) ? __ldg(bh + cc + 1) : 0.f;
            if (r0 < ROWS) {
                qs[r0 * QK_ST + cc]     = acc[nt][0] + b0;
                qs[r0 * QK_ST + cc + 1] = acc[nt][1] + b1;
            }
            if (r1 < ROWS) {
                qs[r1 * QK_ST + cc]     = acc[nt][2] + b0;
                qs[r1 * QK_ST + cc + 1] = acc[nt][3] + b1;
            }
        }
    }
    __syncthreads();

    // ---- phase 2: e = Wa . tanh(q_i + k_j) + ba + mask (transposed store) ----
    const int wg   = tid >> 7;           // batch within CTA (0/1)
    const int t128 = tid & 127;

    float sWa = 0.f;
    #pragma unroll
    for (int u = 0; u < UNITS; u++) sWa += was[u];

    for (int p = t128; p < SEQ * SEQ; p += 128) {
        int i = p / SEQ;
        int j = p - i * SEQ;
        const float4* qi = (const float4*)&qs[(wg * SEQ + i) * QK_ST];
        const float4* kj = (const float4*)&qs[(wg * SEQ + j) * QK_ST + UNITS];
        const float4* wa4 = (const float4*)was;
        float s = 0.f;
        #pragma unroll
        for (int u4 = 0; u4 < UNITS / 4; u4++) {
            float4 q = qi[u4];
            float4 k = kj[u4];
            float4 wa = wa4[u4];
            s = fmaf(wa.x, rcp_fast(__expf(2.f * (q.x + k.x)) + 1.f), s);
            s = fmaf(wa.y, rcp_fast(__expf(2.f * (q.y + k.y)) + 1.f), s);
            s = fmaf(wa.z, rcp_fast(__expf(2.f * (q.z + k.z)) + 1.f), s);
            s = fmaf(wa.w, rcp_fast(__expf(2.f * (q.w + k.w)) + 1.f), s);
        }
        float mask = (i == j) ? -10000.f : -fabsf((float)(i - j));
        eat[wg * SEQ * EAT_ST + j * EAT_ST + i] = sWa - 2.f * s + bav + mask;
    }
    __syncthreads();

    // ---- softmax over j (per batch, lane-per-row) ----
    if (t128 < SEQ) {
        const int i = t128;
        float* eb = eat + wg * SEQ * EAT_ST;
        float m = -1e30f;
        #pragma unroll
        for (int j = 0; j < SEQ; j++) m = fmaxf(m, eb[j * EAT_ST + i]);
        float ex[SEQ];
        float sum = 0.f;
        #pragma unroll
        for (int j = 0; j < SEQ; j++) {
            ex[j] = __expf(eb[j * EAT_ST + i] - m);
            sum += ex[j];
        }
        float inv = 1.f / sum;
        #pragma unroll
        for (int j = 0; j < SEQ; j++) eb[j * EAT_ST + i] = ex[j] * inv;
    }
    __syncthreads();

    // ---- phase 3: v = a @ x  (x from smem, float4 accumulators) ----
    // warp w: batch wb = w>>2, column slice cs = w&3 (128 cols)
    const int wb  = w >> 2;
    const int col = (w & 3) * 128 + lane * 4;
    const float* eb = eat + wb * SEQ * EAT_ST;

    float4 av[SEQ];
    #pragma unroll
    for (int i = 0; i < SEQ; i++) av[i] = make_float4(0.f, 0.f, 0.f, 0.f);

    #pragma unroll
    for (int j = 0; j < SEQ; j++) {
        float4 xj = *(const float4*)(xs + (wb * SEQ + j) * XS_ST + col);
        const float4* arow = (const float4*)&eb[j * EAT_ST];
        float4 A0 = arow[0];
        float4 A1 = arow[1];
        float4 A2 = arow[2];
        float4 A3 = arow[3];   // .w unused
        av[0].x  = fmaf(A0.x, xj.x, av[0].x);  av[0].y  = fmaf(A0.x, xj.y, av[0].y);
        av[0].z  = fmaf(A0.x, xj.z, av[0].z);  av[0].w  = fmaf(A0.x, xj.w, av[0].w);
        av[1].x  = fmaf(A0.y, xj.x, av[1].x);  av[1].y  = fmaf(A0.y, xj.y, av[1].y);
        av[1].z  = fmaf(A0.y, xj.z, av[1].z);  av[1].w  = fmaf(A0.y, xj.w, av[1].w);
        av[2].x  = fmaf(A0.z, xj.x, av[2].x);  av[2].y  = fmaf(A0.z, xj.y, av[2].y);
        av[2].z  = fmaf(A0.z, xj.z, av[2].z);  av[2].w  = fmaf(A0.z, xj.w, av[2].w);
        av[3].x  = fmaf(A0.w, xj.x, av[3].x);  av[3].y  = fmaf(A0.w, xj.y, av[3].y);
        av[3].z  = fmaf(A0.w, xj.z, av[3].z);  av[3].w  = fmaf(A0.w, xj.w, av[3].w);
        av[4].x  = fmaf(A1.x, xj.x, av[4].x);  av[4].y  = fmaf(A1.x, xj.y, av[4].y);
        av[4].z  = fmaf(A1.x, xj.z, av[4].z);  av[4].w  = fmaf(A1.x, xj.w, av[4].w);
        av[5].x  = fmaf(A1.y, xj.x, av[5].x);  av[5].y  = fmaf(A1.y, xj.y, av[5].y);
        av[5].z  = fmaf(A1.y, xj.z, av[5].z);  av[5].w  = fmaf(A1.y, xj.w, av[5].w);
        av[6].x  = fmaf(A1.z, xj.x, av[6].x);  av[6].y  = fmaf(A1.z, xj.y, av[6].y);
        av[6].z  = fmaf(A1.z, xj.z, av[6].z);  av[6].w  = fmaf(A1.z, xj.w, av[6].w);
        av[7].x  = fmaf(A1.w, xj.x, av[7].x);  av[7].y  = fmaf(A1.w, xj.y, av[7].y);
        av[7].z  = fmaf(A1.w, xj.z, av[7].z);  av[7].w  = fmaf(A1.w, xj.w, av[7].w);
        av[8].x  = fmaf(A2.x, xj.x, av[8].x);  av[8].y  = fmaf(A2.x, xj.y, av[8].y);
        av[8].z  = fmaf(A2.x, xj.z, av[8].z);  av[8].w  = fmaf(A2.x, xj.w, av[8].w);
        av[9].x  = fmaf(A2.y, xj.x, av[9].x);  av[9].y  = fmaf(A2.y, xj.y, av[9].y);
        av[9].z  = fmaf(A2.y, xj.z, av[9].z);  av[9].w  = fmaf(A2.y, xj.w, av[9].w);
        av[10].x = fmaf(A2.z, xj.x, av[10].x); av[10].y = fmaf(A2.z, xj.y, av[10].y);
        av[10].z = fmaf(A2.z, xj.z, av[10].z); av[10].w = fmaf(A2.z, xj.w, av[10].w);
        av[11].x = fmaf(A2.w, xj.x, av[11].x); av[11].y = fmaf(A2.w, xj.y, av[11].y);
        av[11].z = fmaf(A2.w, xj.z, av[11].z); av[11].w = fmaf(A2.w, xj.w, av[11].w);
        av[12].x = fmaf(A3.x, xj.x, av[12].x); av[12].y = fmaf(A3.x, xj.y, av[12].y);
        av[12].z = fmaf(A3.x, xj.z, av[12].z); av[12].w = fmaf(A3.x, xj.w, av[12].w);
        av[13].x = fmaf(A3.y, xj.x, av[13].x); av[13].y = fmaf(A3.y, xj.y, av[13].y);
        av[13].z = fmaf(A3.y, xj.z, av[13].z); av[13].w = fmaf(A3.y, xj.w, av[13].w);
        av[14].x = fmaf(A3.z, xj.x, av[14].x); av[14].y = fmaf(A3.z, xj.y, av[14].y);
        av[14].z = fmaf(A3.z, xj.z, av[14].z); av[14].w = fmaf(A3.z, xj.w, av[14].w);
    }

    float* ob = out + (rowbase + (long long)wb * SEQ) * DIM;
    #pragma unroll
    for (int i = 0; i < SEQ; i++)
        __stcs((float4*)(ob + i * DIM + col), av[i]);
}

// ================= launch =================
extern "C" void kernel_launch(void* const* d_in, const int* in_sizes, int n_in,
                              void* d_out, int out_size) {
    const float* x  = (const float*)d_in[0];
    const float* Wt = (const float*)d_in[1];
    const float* Wx = (const float*)d_in[2];
    const float* bh = (const float*)d_in[3];
    const float* Wa = (const float*)d_in[4];
    const float* ba = (const float*)d_in[5];
    float* out = (float*)d_out;

    cudaFuncSetAttribute(sda_fused2_kernel,
                         cudaFuncAttributeMaxDynamicSharedMemorySize, SMEM_BYTES);

    sda_fused2_kernel<<<GRID, THREADS, SMEM_BYTES>>>(x, Wt, Wx, bh, Wa, ba, out);
}

// round 8
// speedup vs baseline: 1.2231x; 1.2231x over previous
#include <cuda_runtime.h>
#include <cstdint>
#include <cstddef>

// ---------------- problem constants ----------------
#define BATCH   16384
#define SEQ     15
#define DIM     512
#define UNITS   32
#define NQK     64
#define TOTROWS (BATCH * SEQ)          // 245760

// ---------------- kernel A (GEMM) tiling ----------------
#define A_ROWS    64
#define A_THREADS 256
#define A_GRID    (TOTROWS / A_ROWS)   // 3840
#define KCHUNK    32
#define NCHUNKS   (DIM / KCHUNK)       // 16
#define NSTAGE    3
#define XS_STRIDE 36                   // x tile: [row][k], padded
#define WS_STRIDE 68                   // W tile: [k][n], padded
#define XS_FLOATS (A_ROWS * XS_STRIDE) // 2304
#define WS_FLOATS (KCHUNK * WS_STRIDE) // 2176
#define STAGE_FLOATS (XS_FLOATS + WS_FLOATS)            // 4480
#define A_SMEM_FLOATS (NSTAGE * STAGE_FLOATS)           // 13440
#define A_SMEM_BYTES  (A_SMEM_FLOATS * 4)               // 53760 -> 4 CTAs/SM

// ---------------- kernel B (attention) ----------------
#define B_WARPS   4
#define B_THREADS 128
#define B_GRID    (BATCH / B_WARPS)    // 4096
#define QK_ST     68                   // 16B-aligned rows for float4 LDS
#define EAT_ST    16                   // eat[j][i], i-contiguous

// ---------------- scratch ----------------
__device__ float g_qk[(size_t)TOTROWS * NQK];   // 62.9 MB

// ---------------- helpers ----------------
__device__ __forceinline__ void cp16(void* dst, const void* src) {
    uint32_t d = (uint32_t)__cvta_generic_to_shared(dst);
    asm volatile("cp.async.cg.shared.global [%0], [%1], 16;" :: "r"(d), "l"(src));
}
#define CP_COMMIT() asm volatile("cp.async.commit_group;")
#define CP_WAIT1()  asm volatile("cp.async.wait_group 1;")
#define CP_WAIT0()  asm volatile("cp.async.wait_group 0;")

__device__ __forceinline__ void mma_tf32(float* c,
                                         uint32_t a0, uint32_t a1, uint32_t a2, uint32_t a3,
                                         uint32_t b0, uint32_t b1) {
    asm volatile(
        "mma.sync.aligned.m16n8k8.row.col.f32.tf32.tf32.f32 "
        "{%0,%1,%2,%3}, {%4,%5,%6,%7}, {%8,%9}, {%0,%1,%2,%3};"
        : "+f"(c[0]), "+f"(c[1]), "+f"(c[2]), "+f"(c[3])
        : "r"(a0), "r"(a1), "r"(a2), "r"(a3), "r"(b0), "r"(b1));
}

__device__ __forceinline__ float rcp_fast(float v) {
    float r;
    asm("rcp.approx.f32 %0, %1;" : "=f"(r) : "f"(v));
    return r;
}

// ================= kernel A: qk = x @ [Wt|Wx] + bh =================
// 64-row tiles, 3-stage cp.async pipeline, 4 CTAs/SM.
// warp w: m-tile = w&3 (16 rows), n-half = w>>2 (32 cols).
__global__ __launch_bounds__(A_THREADS, 4)
void gemm_qk_kernel(const float* __restrict__ x,
                    const float* __restrict__ Wt,
                    const float* __restrict__ Wx,
                    const float* __restrict__ bh) {
    extern __shared__ float sm[];

    const int tid  = threadIdx.x;
    const int lane = tid & 31;
    const int w    = tid >> 5;
    const long long rowbase = (long long)blockIdx.x * A_ROWS;

    auto issue = [&](int stage, int kc) {
        float* xs = sm + stage * STAGE_FLOATS;
        float* ws = xs + XS_FLOATS;
        #pragma unroll
        for (int r = 0; r < 2; r++) {
            int f   = tid + A_THREADS * r;   // 0..511 float4 slots
            int row = f >> 3;                // 0..63
            int c4  = f & 7;                 // 0..7
            cp16(xs + row * XS_STRIDE + c4 * 4,
                 x + (rowbase + row) * DIM + kc + c4 * 4);
        }
        #pragma unroll
        for (int r = 0; r < 2; r++) {
            int e  = tid + A_THREADS * r;    // 0..511
            int k  = e >> 4;                 // 0..31
            int n4 = e & 15;                 // 0..15
            const float* src = (n4 < 8)
                ? Wt + (size_t)(kc + k) * UNITS + n4 * 4
                : Wx + (size_t)(kc + k) * UNITS + (n4 - 8) * 4;
            cp16(ws + k * WS_STRIDE + n4 * 4, src);
        }
        CP_COMMIT();
    };

    issue(0, 0);
    issue(1, KCHUNK);

    float acc[4][4];
    #pragma unroll
    for (int n = 0; n < 4; n++)
        #pragma unroll
        for (int q = 0; q < 4; q++) acc[n][q] = 0.f;

    const int mt = w & 3;                // m-tile: rows mt*16..+15
    const int nh = w >> 2;               // n-half: cols nh*32..+31
    const int g  = lane >> 2;
    const int tg = lane & 3;

    int stage = 0;
    for (int c = 0; c < NCHUNKS; c++) {
        if (c == NCHUNKS - 1) { CP_WAIT0(); } else { CP_WAIT1(); }
        __syncthreads();   // chunk c visible; readers of reissue buf done

        if (c + 2 < NCHUNKS) {
            int nsg = stage + 2; if (nsg >= NSTAGE) nsg -= NSTAGE;
            issue(nsg, (c + 2) * KCHUNK);
        }

        float* xs = sm + stage * STAGE_FLOATS;
        float* ws = xs + XS_FLOATS;

        #pragma unroll
        for (int k8 = 0; k8 < 4; k8++) {
            const int kb = k8 * 8;
            const float* ar = xs + (mt * 16 + g) * XS_STRIDE + kb + tg;
            uint32_t a0 = __float_as_uint(ar[0]);
            uint32_t a1 = __float_as_uint(ar[8 * XS_STRIDE]);
            uint32_t a2 = __float_as_uint(ar[4]);
            uint32_t a3 = __float_as_uint(ar[8 * XS_STRIDE + 4]);
            const float* br = ws + (kb + tg) * WS_STRIDE + nh * 32 + g;
            #pragma unroll
            for (int nt = 0; nt < 4; nt++) {
                mma_tf32(acc[nt], a0, a1, a2, a3,
                         __float_as_uint(br[nt * 8]),
                         __float_as_uint(br[4 * WS_STRIDE + nt * 8]));
            }
        }
        if (++stage >= NSTAGE) stage -= NSTAGE;
    }

    const int r0 = mt * 16 + g;
    const int r1 = r0 + 8;
    #pragma unroll
    for (int nt = 0; nt < 4; nt++) {
        int cc = nh * 32 + nt * 8 + tg * 2;
        float b0 = (cc     < UNITS) ? __ldg(bh + cc)     : 0.f;
        float b1 = (cc + 1 < UNITS) ? __ldg(bh + cc + 1) : 0.f;
        float2 v0 = make_float2(acc[nt][0] + b0, acc[nt][1] + b1);
        float2 v1 = make_float2(acc[nt][2] + b0, acc[nt][3] + b1);
        *(float2*)(g_qk + (size_t)(rowbase + r0) * NQK + cc) = v0;
        *(float2*)(g_qk + (size_t)(rowbase + r1) * NQK + cc) = v1;
    }
}

// ================= kernel B: e/softmax/AV =================
__global__ __launch_bounds__(B_THREADS, 8)
void attn_kernel(const float* __restrict__ x,
                 const float* __restrict__ Wa,
                 const float* __restrict__ ba,
                 float* __restrict__ out) {
    __shared__ float qs[B_WARPS][SEQ * QK_ST];
    __shared__ float eat[B_WARPS][SEQ * EAT_ST];  // eat[w][j*16 + i]
    __shared__ float was[UNITS];

    const int tid  = threadIdx.x;
    const int lane = tid & 31;
    const int w    = tid >> 5;
    const int batch = blockIdx.x * B_WARPS + w;

    if (tid < UNITS) was[tid] = Wa[tid];
    const float bav = __ldg(ba);
    __syncthreads();

    // ---- stage qk[15][64] for this batch (L2-hot after gemm) ----
    const float* qg = g_qk + (size_t)batch * SEQ * NQK;
    for (int p = lane; p < SEQ * NQK / 4; p += 32) {
        float4 v = *(const float4*)(qg + p * 4);
        int row = p >> 4;
        int c4  = p & 15;
        *(float4*)&qs[w][row * QK_ST + c4 * 4] = v;
    }
    __syncwarp();

    float sWa = 0.f;
    #pragma unroll
    for (int u = 0; u < UNITS; u++) sWa += was[u];

    // ---- e = Wa . tanh(q_i + k_j) + ba + mask  (written TRANSPOSED) ----
    // tanh(z) = 1 - 2/(exp(2z)+1)
    for (int p = lane; p < SEQ * SEQ; p += 32) {
        int i = p / SEQ;
        int j = p - i * SEQ;
        const float4* qi = (const float4*)&qs[w][i * QK_ST];
        const float4* kj = (const float4*)&qs[w][j * QK_ST + UNITS];
        const float4* wa4 = (const float4*)was;
        float s = 0.f;
        #pragma unroll
        for (int u4 = 0; u4 < UNITS / 4; u4++) {
            float4 q = qi[u4];
            float4 k = kj[u4];
            float4 wa = wa4[u4];
            s = fmaf(wa.x, rcp_fast(__expf(2.f * (q.x + k.x)) + 1.f), s);
            s = fmaf(wa.y, rcp_fast(__expf(2.f * (q.y + k.y)) + 1.f), s);
            s = fmaf(wa.z, rcp_fast(__expf(2.f * (q.z + k.z)) + 1.f), s);
            s = fmaf(wa.w, rcp_fast(__expf(2.f * (q.w + k.w)) + 1.f), s);
        }
        float mask = (i == j) ? -10000.f : -fabsf((float)(i - j));
        eat[w][j * EAT_ST + i] = sWa - 2.f * s + bav + mask;
    }
    __syncwarp();

    // ---- softmax over j (lane i owns row i) ----
    if (lane < SEQ) {
        const int i = lane;
        float m = -1e30f;
        #pragma unroll
        for (int j = 0; j < SEQ; j++) m = fmaxf(m, eat[w][j * EAT_ST + i]);
        float ex[SEQ];
        float sum = 0.f;
        #pragma unroll
        for (int j = 0; j < SEQ; j++) {
            ex[j] = __expf(eat[w][j * EAT_ST + i] - m);
            sum += ex[j];
        }
        float inv = 1.f / sum;
        #pragma unroll
        for (int j = 0; j < SEQ; j++) eat[w][j * EAT_ST + i] = ex[j] * inv;
    }
    __syncwarp();

    // ---- v = a @ x : float2 accumulators, a rows loaded as float4 ----
    const float* xb = x   + (size_t)batch * SEQ * DIM;
    float*       ob = out + (size_t)batch * SEQ * DIM;

    #pragma unroll 1
    for (int dc = 0; dc < DIM; dc += 64) {
        const int col = dc + lane * 2;
        float2 av[SEQ];
        #pragma unroll
        for (int i = 0; i < SEQ; i++) av[i] = make_float2(0.f, 0.f);

        #pragma unroll
        for (int j = 0; j < SEQ; j++) {
            float2 xj = __ldcs((const float2*)(xb + j * DIM + col));
            const float4* arow = (const float4*)&eat[w][j * EAT_ST];
            float4 A0 = arow[0];
            float4 A1 = arow[1];
            float4 A2 = arow[2];
            float4 A3 = arow[3];
            av[0].x  = fmaf(A0.x, xj.x, av[0].x);  av[0].y  = fmaf(A0.x, xj.y, av[0].y);
            av[1].x  = fmaf(A0.y, xj.x, av[1].x);  av[1].y  = fmaf(A0.y, xj.y, av[1].y);
            av[2].x  = fmaf(A0.z, xj.x, av[2].x);  av[2].y  = fmaf(A0.z, xj.y, av[2].y);
            av[3].x  = fmaf(A0.w, xj.x, av[3].x);  av[3].y  = fmaf(A0.w, xj.y, av[3].y);
            av[4].x  = fmaf(A1.x, xj.x, av[4].x);  av[4].y  = fmaf(A1.x, xj.y, av[4].y);
            av[5].x  = fmaf(A1.y, xj.x, av[5].x);  av[5].y  = fmaf(A1.y, xj.y, av[5].y);
            av[6].x  = fmaf(A1.z, xj.x, av[6].x);  av[6].y  = fmaf(A1.z, xj.y, av[6].y);
            av[7].x  = fmaf(A1.w, xj.x, av[7].x);  av[7].y  = fmaf(A1.w, xj.y, av[7].y);
            av[8].x  = fmaf(A2.x, xj.x, av[8].x);  av[8].y  = fmaf(A2.x, xj.y, av[8].y);
            av[9].x  = fmaf(A2.y, xj.x, av[9].x);  av[9].y  = fmaf(A2.y, xj.y, av[9].y);
            av[10].x = fmaf(A2.z, xj.x, av[10].x); av[10].y = fmaf(A2.z, xj.y, av[10].y);
            av[11].x = fmaf(A2.w, xj.x, av[11].x); av[11].y = fmaf(A2.w, xj.y, av[11].y);
            av[12].x = fmaf(A3.x, xj.x, av[12].x); av[12].y = fmaf(A3.x, xj.y, av[12].y);
            av[13].x = fmaf(A3.y, xj.x, av[13].x); av[13].y = fmaf(A3.y, xj.y, av[13].y);
            av[14].x = fmaf(A3.z, xj.x, av[14].x); av[14].y = fmaf(A3.z, xj.y, av[14].y);
        }
        #pragma unroll
        for (int i = 0; i < SEQ; i++)
            __stcs((float2*)(ob + i * DIM + col), av[i]);
    }
}

// ================= launch =================
extern "C" void kernel_launch(void* const* d_in, const int* in_sizes, int n_in,
                              void* d_out, int out_size) {
    const float* x  = (const float*)d_in[0];
    const float* Wt = (const float*)d_in[1];
    const float* Wx = (const float*)d_in[2];
    const float* bh = (const float*)d_in[3];
    const float* Wa = (const float*)d_in[4];
    const float* ba = (const float*)d_in[5];
    float* out = (float*)d_out;

    cudaFuncSetAttribute(gemm_qk_kernel,
                         cudaFuncAttributeMaxDynamicSharedMemorySize, A_SMEM_BYTES);

    gemm_qk_kernel<<<A_GRID, A_THREADS, A_SMEM_BYTES>>>(x, Wt, Wx, bh);
    attn_kernel<<<B_GRID, B_THREADS>>>(x, Wa, ba, out);
}